// round 1
// baseline (speedup 1.0000x reference)
#include <cuda_runtime.h>
#include <cuda_bf16.h>
#include <math.h>

// Problem constants
#define LSEQ   4096
#define WIN    5
#define NC     4086           // number of centers = LSEQ - 2*WIN
#define NCPAD  4096
#define VOCAB  32000
#define DIM    128
#define VS     8              // vocab splits
#define VC     (VOCAB / VS)   // 4000 vocab rows per split
#define MTILE  32
#define NMT    (NCPAD / MTILE) // 128 m-tiles

// Scratch (no allocations allowed)
__device__ int   d_is64;
__device__ int   d_tok[LSEQ];
__device__ float d_ctx[NCPAD * DIM];
__device__ float d_tgtlogit[NCPAD];
__device__ float d_partial[VS * NCPAD];

// ---------------------------------------------------------------------------
// Detect whether tokens arrived as int64 (odd int32 words all zero) or int32.
__global__ void detect_kernel(const void* __restrict__ toks) {
    const int* p = (const int*)toks;
    int any = 0;
#pragma unroll
    for (int i = 0; i < 16; ++i) any |= p[2 * i + 1];
    d_is64 = (any == 0) ? 1 : 0;
}

__global__ void convert_kernel(const void* __restrict__ toks) {
    int i = blockIdx.x * blockDim.x + threadIdx.x;
    if (i >= LSEQ) return;
    if (d_is64) d_tok[i] = (int)(((const long long*)toks)[i]);
    else        d_tok[i] = ((const int*)toks)[i];
}

// ---------------------------------------------------------------------------
// ctx_mean for each center (padded rows -> 0)
__global__ void ctx_kernel(const float* __restrict__ emb) {
    int c = blockIdx.x;      // 0..NCPAD-1
    int d = threadIdx.x;     // 0..127
    float s = 0.f;
    if (c < NC) {
#pragma unroll
        for (int j = 0; j < 2 * WIN; ++j) {
            int off = (j < WIN) ? (j - WIN) : (j - WIN + 1);  // -5..-1, 1..5
            int t = d_tok[c + WIN + off];
            s += emb[(size_t)t * DIM + d];
        }
        s *= (1.0f / (2 * WIN));
    }
    d_ctx[c * DIM + d] = s;
}

// ---------------------------------------------------------------------------
// Target logits: dot(ctx_mean[c], W[tgt[c]]) per center, one warp per center.
__global__ void tgt_kernel(const float* __restrict__ Wm) {
    int gw   = (blockIdx.x * blockDim.x + threadIdx.x) >> 5;
    int lane = threadIdx.x & 31;
    if (gw >= NC) return;
    int tgt = d_tok[gw + WIN];
    const float4* wr = (const float4*)(Wm + (size_t)tgt * DIM);
    const float4* cr = (const float4*)(d_ctx + (size_t)gw * DIM);
    float4 w = wr[lane];
    float4 c = cr[lane];
    float p = w.x * c.x + w.y * c.y + w.z * c.z + w.w * c.w;
#pragma unroll
    for (int o = 16; o; o >>= 1) p += __shfl_xor_sync(0xffffffffu, p, o);
    if (lane == 0) d_tgtlogit[gw] = p;
}

// ---------------------------------------------------------------------------
// Fused GEMM + sum-exp. Block = (vsplit, mtile): 32 centers x 4000 vocab rows.
__global__ void __launch_bounds__(256, 2) sumexp_kernel(const float* __restrict__ Wm) {
    int vs    = blockIdx.x;
    int mtile = blockIdx.y;
    int tid   = threadIdx.x;

    __shared__ float4 sctx[MTILE][DIM / 4];     // 16 KB
    __shared__ float  sred[MTILE][9];           // warp partials (padded)

    const float4* g = (const float4*)(d_ctx + (size_t)mtile * MTILE * DIM);
    for (int i = tid; i < MTILE * (DIM / 4); i += 256)
        ((float4*)sctx)[i] = g[i];
    __syncthreads();

    float sumexp[MTILE];
#pragma unroll
    for (int m = 0; m < MTILE; ++m) sumexp[m] = 0.f;

    int v0 = vs * VC;
    for (int v = v0 + tid; v < v0 + VC; v += 256) {
        const float4* wr = (const float4*)(Wm + (size_t)v * DIM);
        float acc[MTILE];
#pragma unroll
        for (int m = 0; m < MTILE; ++m) acc[m] = 0.f;

#pragma unroll 2
        for (int k4 = 0; k4 < DIM / 4; ++k4) {
            float4 w = wr[k4];
#pragma unroll
            for (int m = 0; m < MTILE; ++m) {
                float4 c = sctx[m][k4];
                float a = acc[m];
                a = fmaf(w.x, c.x, a);
                a = fmaf(w.y, c.y, a);
                a = fmaf(w.z, c.z, a);
                a = fmaf(w.w, c.w, a);
                acc[m] = a;
            }
        }
#pragma unroll
        for (int m = 0; m < MTILE; ++m) sumexp[m] += __expf(acc[m]);
    }

    // Deterministic block reduction: warp shuffle, then fixed-order combine.
    int lane = tid & 31, wid = tid >> 5;
#pragma unroll
    for (int m = 0; m < MTILE; ++m) {
        float x = sumexp[m];
#pragma unroll
        for (int o = 16; o; o >>= 1) x += __shfl_xor_sync(0xffffffffu, x, o);
        if (lane == 0) sred[m][wid] = x;
    }
    __syncthreads();
    if (tid < MTILE) {
        float t = 0.f;
#pragma unroll
        for (int w2 = 0; w2 < 8; ++w2) t += sred[tid][w2];
        d_partial[vs * NCPAD + mtile * MTILE + tid] = t;
    }
}

// ---------------------------------------------------------------------------
// Final: loss = sum_c [ log(sum_vs partial) - tgtlogit[c] ]
__global__ void final_kernel(float* __restrict__ out) {
    __shared__ float sred[512];
    int tid = threadIdx.x;
    float s = 0.f;
    for (int c = tid; c < NC; c += 512) {
        float t = 0.f;
#pragma unroll
        for (int vs = 0; vs < VS; ++vs) t += d_partial[vs * NCPAD + c];
        s += logf(t) - d_tgtlogit[c];
    }
    sred[tid] = s;
    __syncthreads();
#pragma unroll
    for (int o = 256; o; o >>= 1) {
        if (tid < o) sred[tid] += sred[tid + o];
        __syncthreads();
    }
    if (tid == 0) out[0] = sred[0];
}

// ---------------------------------------------------------------------------
extern "C" void kernel_launch(void* const* d_in, const int* in_sizes, int n_in,
                              void* d_out, int out_size) {
    const void*  toks = d_in[0];
    const float* emb  = (const float*)d_in[1];
    const float* Wm   = (const float*)d_in[2];
    float* out = (float*)d_out;

    detect_kernel<<<1, 1>>>(toks);
    convert_kernel<<<LSEQ / 256, 256>>>(toks);
    ctx_kernel<<<NCPAD, DIM>>>(emb);
    tgt_kernel<<<(NC * 32 + 255) / 256, 256>>>(Wm);
    sumexp_kernel<<<dim3(VS, NMT), 256>>>(Wm);
    final_kernel<<<1, 512>>>(out);
}

// round 3
// speedup vs baseline: 11.7353x; 11.7353x over previous
#include <cuda_runtime.h>
#include <cuda_bf16.h>
#include <math.h>
#include <stdint.h>

// ---------------- problem constants ----------------
#define LSEQ   4096
#define WIN    5
#define NC     4086
#define NCPAD  4096
#define VOCAB  32000
#define DIM    128
#define MT     32              // m-tiles (128 centers each)
#define VG     25              // vocab groups
#define NTPC   10              // 128-wide vocab tiles per CTA
#define NUNITS (MT * VG)       // 800
#define LOG2E  1.4426950408889634f

// ---------------- device scratch ----------------
__device__ int            d_is64;
__device__ int            d_tok[LSEQ];
__device__ float          d_ctx[NCPAD * DIM];
__device__ __nv_bfloat16  d_ctxh[NCPAD * DIM];   // bf16(ctx * log2e)
__device__ __nv_bfloat16  d_Wh[VOCAB * DIM];     // bf16(W)
__device__ float          d_tgtlogit[NCPAD];
__device__ float          d_partialU[NUNITS * 128];

// ---------------- asm helpers ----------------
__device__ __forceinline__ uint32_t smem_to_u32(const void* p) {
    uint32_t a;
    asm("{ .reg .u64 t; cvta.to.shared.u64 t, %1; cvt.u32.u64 %0, t; }" : "=r"(a) : "l"(p));
    return a;
}
#define CP_ASYNC16(dst, src) \
    asm volatile("cp.async.cg.shared.global [%0], [%1], 16;" :: "r"(dst), "l"(src))
#define CP_COMMIT() asm volatile("cp.async.commit_group;" ::: "memory")
#define CP_WAIT1()  asm volatile("cp.async.wait_group 1;" ::: "memory")

__device__ __forceinline__ void ldsm_x4(uint32_t& r0, uint32_t& r1, uint32_t& r2,
                                        uint32_t& r3, uint32_t addr) {
    asm volatile("ldmatrix.sync.aligned.m8n8.x4.shared.b16 {%0,%1,%2,%3}, [%4];"
                 : "=r"(r0), "=r"(r1), "=r"(r2), "=r"(r3) : "r"(addr));
}
__device__ __forceinline__ void mma_bf16(float* c, const uint32_t* a, const uint32_t* b) {
    asm volatile("mma.sync.aligned.m16n8k16.row.col.f32.bf16.bf16.f32 "
                 "{%0,%1,%2,%3}, {%4,%5,%6,%7}, {%8,%9}, {%0,%1,%2,%3};"
                 : "+f"(c[0]), "+f"(c[1]), "+f"(c[2]), "+f"(c[3])
                 : "r"(a[0]), "r"(a[1]), "r"(a[2]), "r"(a[3]), "r"(b[0]), "r"(b[1]));
}
__device__ __forceinline__ float ex2(float x) {
    float y;
    asm("ex2.approx.f32 %0, %1;" : "=f"(y) : "f"(x));
    return y;
}

// ---------------- prep kernels ----------------
__global__ void detect_kernel(const void* __restrict__ toks) {
    const int* p = (const int*)toks;
    int any = 0;
#pragma unroll
    for (int i = 0; i < 16; ++i) any |= p[2 * i + 1];
    d_is64 = (any == 0) ? 1 : 0;
}
__global__ void convert_kernel(const void* __restrict__ toks) {
    int i = blockIdx.x * blockDim.x + threadIdx.x;
    if (i >= LSEQ) return;
    if (d_is64) d_tok[i] = (int)(((const long long*)toks)[i]);
    else        d_tok[i] = ((const int*)toks)[i];
}
__global__ void ctx_kernel(const float* __restrict__ emb) {
    int c = blockIdx.x, d = threadIdx.x;
    float s = 0.f;
    if (c < NC) {
#pragma unroll
        for (int j = 0; j < 2 * WIN; ++j) {
            int off = (j < WIN) ? (j - WIN) : (j - WIN + 1);
            int t = d_tok[c + WIN + off];
            s += emb[(size_t)t * DIM + d];
        }
        s *= (1.0f / (2 * WIN));
    }
    d_ctx[c * DIM + d]  = s;
    d_ctxh[c * DIM + d] = __float2bfloat16(s * LOG2E);
}
__global__ void wconv_kernel(const float* __restrict__ Wm) {
    int i = blockIdx.x * blockDim.x + threadIdx.x;  // over VOCAB*DIM/8
    if (i >= VOCAB * DIM / 8) return;
    float4 w0 = ((const float4*)Wm)[2 * i];
    float4 w1 = ((const float4*)Wm)[2 * i + 1];
    ushort4 o;
    o.x = (__bfloat16_as_ushort(__float2bfloat16(w0.y)) << 16) >> 16 ;
    // pack 8 bf16 into uint4
    uint4 v;
    v.x = ((uint32_t)__bfloat16_as_ushort(__float2bfloat16(w0.y)) << 16) | __bfloat16_as_ushort(__float2bfloat16(w0.x));
    v.y = ((uint32_t)__bfloat16_as_ushort(__float2bfloat16(w0.w)) << 16) | __bfloat16_as_ushort(__float2bfloat16(w0.z));
    v.z = ((uint32_t)__bfloat16_as_ushort(__float2bfloat16(w1.y)) << 16) | __bfloat16_as_ushort(__float2bfloat16(w1.x));
    v.w = ((uint32_t)__bfloat16_as_ushort(__float2bfloat16(w1.w)) << 16) | __bfloat16_as_ushort(__float2bfloat16(w1.z));
    ((uint4*)d_Wh)[i] = v;
}
__global__ void tgt_kernel(const float* __restrict__ Wm) {
    int gw = (blockIdx.x * blockDim.x + threadIdx.x) >> 5;
    int lane = threadIdx.x & 31;
    if (gw >= NC) return;
    int tgt = d_tok[gw + WIN];
    float4 w = ((const float4*)(Wm + (size_t)tgt * DIM))[lane];
    float4 c = ((const float4*)(d_ctx + (size_t)gw * DIM))[lane];
    float p = w.x * c.x + w.y * c.y + w.z * c.z + w.w * c.w;
#pragma unroll
    for (int o = 16; o; o >>= 1) p += __shfl_xor_sync(0xffffffffu, p, o);
    if (lane == 0) d_tgtlogit[gw] = p;
}

// ---------------- main fused GEMM + sum-exp (mma.sync bf16) ----------------
// 256 threads = 8 warps; warp_m = wid&3 (32 rows each), warp_n = wid>>2 (64 cols each)
// smem: A 32KB | B 2x32KB (double buffer). sred reuses A region at the end.
#define SMEM_A_OFF 0
#define SMEM_B_OFF 32768
#define SMEM_MAIN  (32768 + 2 * 32768)

__global__ void __launch_bounds__(256, 1) gemm_sumexp_kernel() {
    extern __shared__ char smem[];
    uint32_t sb = smem_to_u32(smem);
    const int tid  = threadIdx.x;
    const int lane = tid & 31;
    const int wid  = tid >> 5;
    const int warp_m = wid & 3;
    const int warp_n = wid >> 2;
    const int mtile = blockIdx.x;
    const int vgrp  = blockIdx.y;

    const uint32_t sA = sb + SMEM_A_OFF;
    const uint32_t sB = sb + SMEM_B_OFF;

    // ---- async-load A tile (128x128 bf16, swizzled) ----
    {
        const char* src = (const char*)(d_ctxh + (size_t)mtile * 128 * DIM);
#pragma unroll
        for (int i = 0; i < 8; ++i) {
            int j = tid + i * 256;
            int row = j >> 4, cb = j & 15;
            CP_ASYNC16(sA + row * 256 + ((cb ^ (row & 7)) << 4),
                       src + row * 256 + cb * 16);
        }
    }
    // ---- B tile loader ----
    auto loadB = [&](int t) {
        const char* src = (const char*)(d_Wh + (size_t)(vgrp * NTPC + t) * 128 * DIM);
        uint32_t dstb = sB + (t & 1) * 32768;
#pragma unroll
        for (int i = 0; i < 8; ++i) {
            int j = tid + i * 256;
            int row = j >> 4, cb = j & 15;
            CP_ASYNC16(dstb + row * 256 + ((cb ^ (row & 7)) << 4),
                       src + row * 256 + cb * 16);
        }
    };
    loadB(0); CP_COMMIT();   // group: A + tile0
    loadB(1); CP_COMMIT();   // group: tile1

    uint32_t Afrag[2][8][4];
    float su[2][2] = {{0.f, 0.f}, {0.f, 0.f}};

    for (int t = 0; t < NTPC; ++t) {
        CP_WAIT1();
        __syncthreads();
        if (t == 0) {
            // load persistent A fragments
#pragma unroll
            for (int ms = 0; ms < 2; ++ms)
#pragma unroll
                for (int ks = 0; ks < 8; ++ks) {
                    int row = warp_m * 32 + ms * 16 + (lane & 7) + 8 * ((lane >> 3) & 1);
                    int cb  = ks * 2 + (lane >> 4);
                    uint32_t addr = sA + row * 256 + ((cb ^ (row & 7)) << 4);
                    ldsm_x4(Afrag[ms][ks][0], Afrag[ms][ks][1],
                            Afrag[ms][ks][2], Afrag[ms][ks][3], addr);
                }
        }
        uint32_t bufb = sB + (t & 1) * 32768;

        // process n8-subtiles in pairs (4 independent mma chains)
#pragma unroll
        for (int jp = 0; jp < 4; ++jp) {
            uint32_t Bf[2][8][2];
#pragma unroll
            for (int jj = 0; jj < 2; ++jj) {
                int j = jp * 2 + jj;
#pragma unroll
                for (int kk = 0; kk < 4; ++kk) {
                    int row = warp_n * 64 + j * 8 + (lane & 7);
                    int cb  = kk * 4 + (lane >> 3);
                    uint32_t addr = bufb + row * 256 + ((cb ^ (row & 7)) << 4);
                    ldsm_x4(Bf[jj][2 * kk][0], Bf[jj][2 * kk][1],
                            Bf[jj][2 * kk + 1][0], Bf[jj][2 * kk + 1][1], addr);
                }
            }
            float C[2][2][4];
#pragma unroll
            for (int ms = 0; ms < 2; ++ms)
#pragma unroll
                for (int jj = 0; jj < 2; ++jj)
#pragma unroll
                    for (int q = 0; q < 4; ++q) C[ms][jj][q] = 0.f;
#pragma unroll
            for (int ks = 0; ks < 8; ++ks)
#pragma unroll
                for (int ms = 0; ms < 2; ++ms)
#pragma unroll
                    for (int jj = 0; jj < 2; ++jj)
                        mma_bf16(C[ms][jj], Afrag[ms][ks], Bf[jj][ks]);
            // epilogue: exp2 and accumulate per-row
#pragma unroll
            for (int ms = 0; ms < 2; ++ms)
#pragma unroll
                for (int jj = 0; jj < 2; ++jj) {
                    su[ms][0] += ex2(C[ms][jj][0]) + ex2(C[ms][jj][1]);
                    su[ms][1] += ex2(C[ms][jj][2]) + ex2(C[ms][jj][3]);
                }
        }
        __syncthreads();
        if (t + 2 < NTPC) { loadB(t + 2); CP_COMMIT(); }
    }

    // ---- deterministic reduction: quad shuffle, smem combine ----
#pragma unroll
    for (int ms = 0; ms < 2; ++ms)
#pragma unroll
        for (int h = 0; h < 2; ++h) {
            float x = su[ms][h];
            x += __shfl_xor_sync(0xffffffffu, x, 1);
            x += __shfl_xor_sync(0xffffffffu, x, 2);
            su[ms][h] = x;
        }
    float* sred = (float*)smem;   // reuse A region (all warps past A reads)
    if ((lane & 3) == 0) {
#pragma unroll
        for (int ms = 0; ms < 2; ++ms)
#pragma unroll
            for (int h = 0; h < 2; ++h) {
                int srow = warp_m * 32 + ms * 16 + h * 8 + (lane >> 2);
                sred[warp_n * 128 + srow] = su[ms][h];
            }
    }
    __syncthreads();
    if (tid < 128) {
        int u = mtile * VG + vgrp;
        d_partialU[u * 128 + tid] = sred[tid] + sred[128 + tid];
    }
}

// ---------------- final reduction ----------------
__global__ void final_kernel(float* __restrict__ out) {
    __shared__ float sred[512];
    int tid = threadIdx.x;
    float s = 0.f;
    for (int c = tid; c < NC; c += 512) {
        int m = c >> 7, r = c & 127;
        float t = 0.f;
#pragma unroll
        for (int g = 0; g < VG; ++g) t += d_partialU[(m * VG + g) * 128 + r];
        s += logf(t) - d_tgtlogit[c];
    }
    sred[tid] = s;
    __syncthreads();
#pragma unroll
    for (int o = 256; o; o >>= 1) {
        if (tid < o) sred[tid] += sred[tid + o];
        __syncthreads();
    }
    if (tid == 0) out[0] = sred[0];
}

// ---------------- launch ----------------
extern "C" void kernel_launch(void* const* d_in, const int* in_sizes, int n_in,
                              void* d_out, int out_size) {
    const void*  toks = d_in[0];
    const float* emb  = (const float*)d_in[1];
    const float* Wm   = (const float*)d_in[2];
    float* out = (float*)d_out;

    cudaFuncSetAttribute(gemm_sumexp_kernel,
                         cudaFuncAttributeMaxDynamicSharedMemorySize, SMEM_MAIN);

    detect_kernel<<<1, 1>>>(toks);
    convert_kernel<<<LSEQ / 256, 256>>>(toks);
    ctx_kernel<<<NCPAD, DIM>>>(emb);
    wconv_kernel<<<(VOCAB * DIM / 8 + 255) / 256, 256>>>(Wm);
    tgt_kernel<<<(NC * 32 + 255) / 256, 256>>>(Wm);
    gemm_sumexp_kernel<<<dim3(MT, VG), 256, SMEM_MAIN>>>();
    final_kernel<<<1, 512>>>(out);
}

// round 4
// speedup vs baseline: 13.5807x; 1.1572x over previous
#include <cuda_runtime.h>
#include <cuda_bf16.h>
#include <math.h>
#include <stdint.h>

// ---------------- problem constants ----------------
#define LSEQ   4096
#define WIN    5
#define NC     4086
#define NCPAD  4096
#define VOCAB  32000
#define DIM    128
#define MT     32              // m-tiles (128 centers each)
#define NSEG   9               // n-segments per m-tile (7x28 + 2x27 = 250 tiles)
#define NUNITS (MT * NSEG)     // 288 CTAs
#define LOG2E  1.4426950408889634f

// ---------------- device scratch ----------------
__device__ int            d_tok[LSEQ];
__device__ __nv_bfloat16  d_ctxh[NCPAD * DIM];   // bf16(ctx * log2e)
__device__ __nv_bfloat16  d_Wh[VOCAB * DIM];     // bf16(W)
__device__ float          d_tgtlogit[NCPAD];
__device__ float          d_partialU[NUNITS * 128];

// ---------------- asm helpers ----------------
__device__ __forceinline__ uint32_t smem_to_u32(const void* p) {
    uint32_t a;
    asm("{ .reg .u64 t; cvta.to.shared.u64 t, %1; cvt.u32.u64 %0, t; }" : "=r"(a) : "l"(p));
    return a;
}
#define CP_ASYNC16(dst, src) \
    asm volatile("cp.async.cg.shared.global [%0], [%1], 16;" :: "r"(dst), "l"(src))
#define CP_COMMIT() asm volatile("cp.async.commit_group;" ::: "memory")
#define CP_WAIT1()  asm volatile("cp.async.wait_group 1;" ::: "memory")

__device__ __forceinline__ void ldsm_x4(uint32_t& r0, uint32_t& r1, uint32_t& r2,
                                        uint32_t& r3, uint32_t addr) {
    asm volatile("ldmatrix.sync.aligned.m8n8.x4.shared.b16 {%0,%1,%2,%3}, [%4];"
                 : "=r"(r0), "=r"(r1), "=r"(r2), "=r"(r3) : "r"(addr));
}
__device__ __forceinline__ void mma_bf16(float* c, const uint32_t* a, const uint32_t* b) {
    asm volatile("mma.sync.aligned.m16n8k16.row.col.f32.bf16.bf16.f32 "
                 "{%0,%1,%2,%3}, {%4,%5,%6,%7}, {%8,%9}, {%0,%1,%2,%3};"
                 : "+f"(c[0]), "+f"(c[1]), "+f"(c[2]), "+f"(c[3])
                 : "r"(a[0]), "r"(a[1]), "r"(a[2]), "r"(a[3]), "r"(b[0]), "r"(b[1]));
}
__device__ __forceinline__ float ex2(float x) {
    float y;
    asm("ex2.approx.f32 %0, %1;" : "=f"(y) : "f"(x));
    return y;
}

// ---------------- prep kernels ----------------
// convert: per-block int64/int32 detection (deterministic, redundant per block)
__global__ void convert_kernel(const void* __restrict__ toks) {
    __shared__ int s_is64;
    const int* p = (const int*)toks;
    if (threadIdx.x == 0) {
        int any = 0;
#pragma unroll
        for (int i = 0; i < 16; ++i) any |= p[2 * i + 1];
        s_is64 = (any == 0) ? 1 : 0;
    }
    __syncthreads();
    int i = blockIdx.x * blockDim.x + threadIdx.x;
    if (i >= LSEQ) return;
    if (s_is64) d_tok[i] = (int)(((const long long*)toks)[i]);
    else        d_tok[i] = p[i];
}

// ctx + fused target-logit (fp32 exact dot with W[tgt])
__global__ void ctx_kernel(const float* __restrict__ emb, const float* __restrict__ Wm) {
    __shared__ float sred[4];
    int c = blockIdx.x, d = threadIdx.x;
    float s = 0.f;
    if (c < NC) {
#pragma unroll
        for (int j = 0; j < 2 * WIN; ++j) {
            int off = (j < WIN) ? (j - WIN) : (j - WIN + 1);
            int t = d_tok[c + WIN + off];
            s += emb[(size_t)t * DIM + d];
        }
        s *= (1.0f / (2 * WIN));
    }
    d_ctxh[c * DIM + d] = __float2bfloat16(s * LOG2E);
    if (c < NC) {
        int tgt = d_tok[c + WIN];
        float pr = s * Wm[(size_t)tgt * DIM + d];
#pragma unroll
        for (int o = 16; o; o >>= 1) pr += __shfl_xor_sync(0xffffffffu, pr, o);
        if ((d & 31) == 0) sred[d >> 5] = pr;
        __syncthreads();
        if (d == 0) d_tgtlogit[c] = sred[0] + sred[1] + sred[2] + sred[3];
    }
}

__global__ void wconv_kernel(const float* __restrict__ Wm) {
    int i = blockIdx.x * blockDim.x + threadIdx.x;  // over VOCAB*DIM/8
    if (i >= VOCAB * DIM / 8) return;
    float4 w0 = ((const float4*)Wm)[2 * i];
    float4 w1 = ((const float4*)Wm)[2 * i + 1];
    uint4 v;
    v.x = ((uint32_t)__bfloat16_as_ushort(__float2bfloat16(w0.y)) << 16) | __bfloat16_as_ushort(__float2bfloat16(w0.x));
    v.y = ((uint32_t)__bfloat16_as_ushort(__float2bfloat16(w0.w)) << 16) | __bfloat16_as_ushort(__float2bfloat16(w0.z));
    v.z = ((uint32_t)__bfloat16_as_ushort(__float2bfloat16(w1.y)) << 16) | __bfloat16_as_ushort(__float2bfloat16(w1.x));
    v.w = ((uint32_t)__bfloat16_as_ushort(__float2bfloat16(w1.w)) << 16) | __bfloat16_as_ushort(__float2bfloat16(w1.z));
    ((uint4*)d_Wh)[i] = v;
}

// ---------------- main fused GEMM + sum-exp (mma.sync bf16) ----------------
// grid (MT, NSEG): 288 CTAs -> 2 nearly-full waves on 148 SMs.
// 256 threads = 8 warps; warp_m = wid&3 (32 rows each), warp_n = wid>>2 (64 cols).
#define SMEM_A_OFF 0
#define SMEM_B_OFF 32768
#define SMEM_MAIN  (32768 + 2 * 32768)

__global__ void __launch_bounds__(256, 1) gemm_sumexp_kernel() {
    extern __shared__ char smem[];
    uint32_t sb = smem_to_u32(smem);
    const int tid  = threadIdx.x;
    const int lane = tid & 31;
    const int wid  = tid >> 5;
    const int warp_m = wid & 3;
    const int warp_n = wid >> 2;
    const int mtile = blockIdx.x;
    const int seg   = blockIdx.y;
    const int nbase = (seg < 7) ? seg * 28 : 196 + (seg - 7) * 27;
    const int len   = (seg < 7) ? 28 : 27;

    const uint32_t sA = sb + SMEM_A_OFF;
    const uint32_t sB = sb + SMEM_B_OFF;

    // ---- async-load A tile (128x128 bf16, swizzled) ----
    {
        const char* src = (const char*)(d_ctxh + (size_t)mtile * 128 * DIM);
#pragma unroll
        for (int i = 0; i < 8; ++i) {
            int j = tid + i * 256;
            int row = j >> 4, cb = j & 15;
            CP_ASYNC16(sA + row * 256 + ((cb ^ (row & 7)) << 4),
                       src + row * 256 + cb * 16);
        }
    }
    // ---- B tile loader ----
    auto loadB = [&](int t) {
        const char* src = (const char*)(d_Wh + (size_t)(nbase + t) * 128 * DIM);
        uint32_t dstb = sB + (t & 1) * 32768;
#pragma unroll
        for (int i = 0; i < 8; ++i) {
            int j = tid + i * 256;
            int row = j >> 4, cb = j & 15;
            CP_ASYNC16(dstb + row * 256 + ((cb ^ (row & 7)) << 4),
                       src + row * 256 + cb * 16);
        }
    };
    loadB(0); CP_COMMIT();   // group: A + tile0
    loadB(1); CP_COMMIT();   // group: tile1

    uint32_t Afrag[2][8][4];
    float su[2][2] = {{0.f, 0.f}, {0.f, 0.f}};

    for (int t = 0; t < len; ++t) {
        CP_WAIT1();
        __syncthreads();
        if (t == 0) {
            // load persistent A fragments
#pragma unroll
            for (int ms = 0; ms < 2; ++ms)
#pragma unroll
                for (int ks = 0; ks < 8; ++ks) {
                    int row = warp_m * 32 + ms * 16 + (lane & 7) + 8 * ((lane >> 3) & 1);
                    int cb  = ks * 2 + (lane >> 4);
                    uint32_t addr = sA + row * 256 + ((cb ^ (row & 7)) << 4);
                    ldsm_x4(Afrag[ms][ks][0], Afrag[ms][ks][1],
                            Afrag[ms][ks][2], Afrag[ms][ks][3], addr);
                }
        }
        uint32_t bufb = sB + (t & 1) * 32768;

        // n8-subtiles in pairs (4 independent mma chains)
#pragma unroll
        for (int jp = 0; jp < 4; ++jp) {
            uint32_t Bf[2][8][2];
#pragma unroll
            for (int jj = 0; jj < 2; ++jj) {
                int j = jp * 2 + jj;
#pragma unroll
                for (int kk = 0; kk < 4; ++kk) {
                    int row = warp_n * 64 + j * 8 + (lane & 7);
                    int cb  = kk * 4 + (lane >> 3);
                    uint32_t addr = bufb + row * 256 + ((cb ^ (row & 7)) << 4);
                    ldsm_x4(Bf[jj][2 * kk][0], Bf[jj][2 * kk][1],
                            Bf[jj][2 * kk + 1][0], Bf[jj][2 * kk + 1][1], addr);
                }
            }
            float C[2][2][4];
#pragma unroll
            for (int ms = 0; ms < 2; ++ms)
#pragma unroll
                for (int jj = 0; jj < 2; ++jj)
#pragma unroll
                    for (int q = 0; q < 4; ++q) C[ms][jj][q] = 0.f;
#pragma unroll
            for (int ks = 0; ks < 8; ++ks)
#pragma unroll
                for (int ms = 0; ms < 2; ++ms)
#pragma unroll
                    for (int jj = 0; jj < 2; ++jj)
                        mma_bf16(C[ms][jj], Afrag[ms][ks], Bf[jj][ks]);
#pragma unroll
            for (int ms = 0; ms < 2; ++ms)
#pragma unroll
                for (int jj = 0; jj < 2; ++jj) {
                    su[ms][0] += ex2(C[ms][jj][0]) + ex2(C[ms][jj][1]);
                    su[ms][1] += ex2(C[ms][jj][2]) + ex2(C[ms][jj][3]);
                }
        }
        __syncthreads();
        if (t + 2 < len) { loadB(t + 2); CP_COMMIT(); }
    }

    // ---- deterministic reduction: quad shuffle, smem combine ----
#pragma unroll
    for (int ms = 0; ms < 2; ++ms)
#pragma unroll
        for (int h = 0; h < 2; ++h) {
            float x = su[ms][h];
            x += __shfl_xor_sync(0xffffffffu, x, 1);
            x += __shfl_xor_sync(0xffffffffu, x, 2);
            su[ms][h] = x;
        }
    float* sred = (float*)smem;   // reuse A region
    if ((lane & 3) == 0) {
#pragma unroll
        for (int ms = 0; ms < 2; ++ms)
#pragma unroll
            for (int h = 0; h < 2; ++h) {
                int srow = warp_m * 32 + ms * 16 + h * 8 + (lane >> 2);
                sred[warp_n * 128 + srow] = su[ms][h];
            }
    }
    __syncthreads();
    if (tid < 128) {
        int u = mtile * NSEG + seg;
        d_partialU[u * 128 + tid] = sred[tid] + sred[128 + tid];
    }
}

// ---------------- final reduction ----------------
__global__ void final_kernel(float* __restrict__ out) {
    __shared__ float sred[512];
    int tid = threadIdx.x;
    float s = 0.f;
    for (int c = tid; c < NC; c += 512) {
        int m = c >> 7, r = c & 127;
        float t = 0.f;
#pragma unroll
        for (int g = 0; g < NSEG; ++g) t += d_partialU[(m * NSEG + g) * 128 + r];
        s += logf(t) - d_tgtlogit[c];
    }
    sred[tid] = s;
    __syncthreads();
#pragma unroll
    for (int o = 256; o; o >>= 1) {
        if (tid < o) sred[tid] += sred[tid + o];
        __syncthreads();
    }
    if (tid == 0) out[0] = sred[0];
}

// ---------------- launch ----------------
extern "C" void kernel_launch(void* const* d_in, const int* in_sizes, int n_in,
                              void* d_out, int out_size) {
    const void*  toks = d_in[0];
    const float* emb  = (const float*)d_in[1];
    const float* Wm   = (const float*)d_in[2];
    float* out = (float*)d_out;

    cudaFuncSetAttribute(gemm_sumexp_kernel,
                         cudaFuncAttributeMaxDynamicSharedMemorySize, SMEM_MAIN);

    convert_kernel<<<LSEQ / 256, 256>>>(toks);
    ctx_kernel<<<NCPAD, DIM>>>(emb, Wm);
    wconv_kernel<<<(VOCAB * DIM / 8 + 255) / 256, 256>>>(Wm);
    gemm_sumexp_kernel<<<dim3(MT, NSEG), 256, SMEM_MAIN>>>();
    final_kernel<<<1, 512>>>(out);
}

// round 5
// speedup vs baseline: 13.7808x; 1.0147x over previous
#include <cuda_runtime.h>
#include <cuda_bf16.h>
#include <math.h>
#include <stdint.h>

// ---------------- problem constants ----------------
#define LSEQ   4096
#define WIN    5
#define NC     4086
#define NCPAD  4096
#define VOCAB  32000
#define DIM    128
#define MT     32              // m-tiles (128 centers each)
#define NSEG   9               // n-segments (7x28 + 2x27 = 250 tiles)
#define NUNITS (MT * NSEG)     // 288 CTAs
#define LOG2E  1.4426950408889634f
#define NEGINF __int_as_float(0xFF800000)

// ---------------- device scratch ----------------
__device__ int            d_tok[LSEQ];
__device__ __nv_bfloat16  d_ctxh[NCPAD * DIM];   // bf16(ctx * log2e)
__device__ __nv_bfloat16  d_Wh[VOCAB * DIM];     // bf16(W)
__device__ float          d_tgtlogit[NCPAD];
__device__ float          d_partialU[NUNITS * 128];

// ---------------- asm helpers ----------------
__device__ __forceinline__ uint32_t smem_to_u32(const void* p) {
    uint32_t a;
    asm("{ .reg .u64 t; cvta.to.shared.u64 t, %1; cvt.u32.u64 %0, t; }" : "=r"(a) : "l"(p));
    return a;
}
#define CP_ASYNC16(dst, src) \
    asm volatile("cp.async.cg.shared.global [%0], [%1], 16;" :: "r"(dst), "l"(src))
#define CP_COMMIT() asm volatile("cp.async.commit_group;" ::: "memory")
#define CP_WAIT1()  asm volatile("cp.async.wait_group 1;" ::: "memory")

__device__ __forceinline__ void ldsm_x4(uint32_t& r0, uint32_t& r1, uint32_t& r2,
                                        uint32_t& r3, uint32_t addr) {
    asm volatile("ldmatrix.sync.aligned.m8n8.x4.shared.b16 {%0,%1,%2,%3}, [%4];"
                 : "=r"(r0), "=r"(r1), "=r"(r2), "=r"(r3) : "r"(addr));
}
__device__ __forceinline__ void mma_bf16(float* c, const uint32_t* a, const uint32_t* b) {
    asm volatile("mma.sync.aligned.m16n8k16.row.col.f32.bf16.bf16.f32 "
                 "{%0,%1,%2,%3}, {%4,%5,%6,%7}, {%8,%9}, {%0,%1,%2,%3};"
                 : "+f"(c[0]), "+f"(c[1]), "+f"(c[2]), "+f"(c[3])
                 : "r"(a[0]), "r"(a[1]), "r"(a[2]), "r"(a[3]), "r"(b[0]), "r"(b[1]));
}
__device__ __forceinline__ float ex2(float x) {
    float y;
    asm("ex2.approx.f32 %0, %1;" : "=f"(y) : "f"(x));
    return y;
}

// ---------------- prep kernels ----------------
__global__ void convert_kernel(const void* __restrict__ toks) {
    __shared__ int s_is64;
    const int* p = (const int*)toks;
    if (threadIdx.x == 0) {
        int any = 0;
#pragma unroll
        for (int i = 0; i < 16; ++i) any |= p[2 * i + 1];
        s_is64 = (any == 0) ? 1 : 0;
    }
    __syncthreads();
    int i = blockIdx.x * blockDim.x + threadIdx.x;
    if (i >= LSEQ) return;
    if (s_is64) d_tok[i] = (int)(((const long long*)toks)[i]);
    else        d_tok[i] = p[i];
}

// fused: blocks [0,NCPAD) do ctx (+target logit), blocks [NCPAD,..) do W->bf16
__global__ void prep_kernel(const float* __restrict__ emb, const float* __restrict__ Wm) {
    if (blockIdx.x < NCPAD) {
        __shared__ float sred[4];
        int c = blockIdx.x, d = threadIdx.x;
        float s = 0.f;
        if (c < NC) {
#pragma unroll
            for (int j = 0; j < 2 * WIN; ++j) {
                int off = (j < WIN) ? (j - WIN) : (j - WIN + 1);
                int t = d_tok[c + WIN + off];
                s += emb[(size_t)t * DIM + d];
            }
            s *= (1.0f / (2 * WIN));
        }
        d_ctxh[c * DIM + d] = __float2bfloat16(s * LOG2E);
        if (c < NC) {
            int tgt = d_tok[c + WIN];
            float pr = s * Wm[(size_t)tgt * DIM + d];
#pragma unroll
            for (int o = 16; o; o >>= 1) pr += __shfl_xor_sync(0xffffffffu, pr, o);
            if ((d & 31) == 0) sred[d >> 5] = pr;
            __syncthreads();
            if (d == 0) d_tgtlogit[c] = sred[0] + sred[1] + sred[2] + sred[3];
        }
    } else {
        int i = (blockIdx.x - NCPAD) * 128 + threadIdx.x;  // uint4 index
        if (i >= VOCAB * DIM / 8) return;
        float4 w0 = ((const float4*)Wm)[2 * i];
        float4 w1 = ((const float4*)Wm)[2 * i + 1];
        uint4 v;
        v.x = ((uint32_t)__bfloat16_as_ushort(__float2bfloat16(w0.y)) << 16) | __bfloat16_as_ushort(__float2bfloat16(w0.x));
        v.y = ((uint32_t)__bfloat16_as_ushort(__float2bfloat16(w0.w)) << 16) | __bfloat16_as_ushort(__float2bfloat16(w0.z));
        v.z = ((uint32_t)__bfloat16_as_ushort(__float2bfloat16(w1.y)) << 16) | __bfloat16_as_ushort(__float2bfloat16(w1.x));
        v.w = ((uint32_t)__bfloat16_as_ushort(__float2bfloat16(w1.w)) << 16) | __bfloat16_as_ushort(__float2bfloat16(w1.z));
        ((uint4*)d_Wh)[i] = v;
    }
}

// ---------------- main fused GEMM + sum-exp ----------------
#define SMEM_A_OFF 0
#define SMEM_B_OFF 32768
#define SMEM_MAIN  (32768 + 2 * 32768)

__global__ void __launch_bounds__(256, 1) gemm_sumexp_kernel() {
    extern __shared__ char smem[];
    uint32_t sb = smem_to_u32(smem);
    const int tid  = threadIdx.x;
    const int lane = tid & 31;
    const int wid  = tid >> 5;
    const int warp_m = wid & 3;
    const int warp_n = wid >> 2;
    const int mtile = blockIdx.x;
    const int seg   = blockIdx.y;
    const int nbase = (seg < 7) ? seg * 28 : 196 + (seg - 7) * 27;
    const int len   = (seg < 7) ? 28 : 27;

    const uint32_t sA = sb + SMEM_A_OFF;
    const uint32_t sB = sb + SMEM_B_OFF;

    // ---- async-load A tile (128x128 bf16, swizzled) ----
    {
        const char* src = (const char*)(d_ctxh + (size_t)mtile * 128 * DIM);
#pragma unroll
        for (int i = 0; i < 8; ++i) {
            int j = tid + i * 256;
            int row = j >> 4, cb = j & 15;
            CP_ASYNC16(sA + row * 256 + ((cb ^ (row & 7)) << 4),
                       src + row * 256 + cb * 16);
        }
    }
    auto loadB = [&](int t) {
        const char* src = (const char*)(d_Wh + (size_t)(nbase + t) * 128 * DIM);
        uint32_t dstb = sB + (t & 1) * 32768;
#pragma unroll
        for (int i = 0; i < 8; ++i) {
            int j = tid + i * 256;
            int row = j >> 4, cb = j & 15;
            CP_ASYNC16(dstb + row * 256 + ((cb ^ (row & 7)) << 4),
                       src + row * 256 + cb * 16);
        }
    };
    loadB(0); CP_COMMIT();
    loadB(1); CP_COMMIT();

    // precomputed B ldsm addressing: row&7 == lane&7 for every (jp,jj)
    const uint32_t rowbase = (uint32_t)(warp_n * 64 + (lane & 7)) * 256;
    uint32_t colsw[4];
#pragma unroll
    for (int kk = 0; kk < 4; ++kk)
        colsw[kk] = (uint32_t)(((kk * 4 + (lane >> 3)) ^ (lane & 7)) << 4);

    uint32_t Afrag[2][8][4];
    uint32_t Bf[2][2][8][2];          // [parity][jj][ks][2]
    float    Cb[2][2][2][4];          // [parity][ms][jj][4]
    float    su[2][2] = {{0.f, 0.f}, {0.f, 0.f}};
#pragma unroll
    for (int p = 0; p < 2; ++p)
#pragma unroll
        for (int ms = 0; ms < 2; ++ms)
#pragma unroll
            for (int jj = 0; jj < 2; ++jj)
#pragma unroll
                for (int q = 0; q < 4; ++q) Cb[p][ms][jj][q] = NEGINF;

    for (int t = 0; t < len; ++t) {
        CP_WAIT1();
        __syncthreads();
        if (t == 0) {
#pragma unroll
            for (int ms = 0; ms < 2; ++ms)
#pragma unroll
                for (int ks = 0; ks < 8; ++ks) {
                    int row = warp_m * 32 + ms * 16 + (lane & 7) + 8 * ((lane >> 3) & 1);
                    int cb  = ks * 2 + (lane >> 4);
                    uint32_t addr = sA + row * 256 + ((cb ^ (row & 7)) << 4);
                    ldsm_x4(Afrag[ms][ks][0], Afrag[ms][ks][1],
                            Afrag[ms][ks][2], Afrag[ms][ks][3], addr);
                }
        }
        const uint32_t tbase = sB + (t & 1) * 32768 + rowbase;

#pragma unroll
        for (int jp = 0; jp < 4; ++jp) {
            const int par = jp & 1;
            // load B fragments for this jp
#pragma unroll
            for (int jj = 0; jj < 2; ++jj) {
                const uint32_t jbase = tbase + (uint32_t)((jp * 16 + jj * 8) * 256);
#pragma unroll
                for (int kk = 0; kk < 4; ++kk)
                    ldsm_x4(Bf[par][jj][2 * kk][0], Bf[par][jj][2 * kk][1],
                            Bf[par][jj][2 * kk + 1][0], Bf[par][jj][2 * kk + 1][1],
                            jbase + colsw[kk]);
            }
            // stash previous-parity C, then reset accumulators
            float P[2][2][4];
#pragma unroll
            for (int ms = 0; ms < 2; ++ms)
#pragma unroll
                for (int jj = 0; jj < 2; ++jj)
#pragma unroll
                    for (int q = 0; q < 4; ++q) {
                        P[ms][jj][q] = Cb[par ^ 1][ms][jj][q];
                        Cb[par][ms][jj][q] = 0.f;
                    }
            // MMA chain for this jp (tensor pipe) interleaved by ptxas with
            // EX2 of previous jp (MUFU pipe) — independent registers.
#pragma unroll
            for (int ks = 0; ks < 8; ++ks)
#pragma unroll
                for (int ms = 0; ms < 2; ++ms)
#pragma unroll
                    for (int jj = 0; jj < 2; ++jj)
                        mma_bf16(Cb[par][ms][jj], Afrag[ms][ks], Bf[par][jj][ks]);
#pragma unroll
            for (int ms = 0; ms < 2; ++ms)
#pragma unroll
                for (int jj = 0; jj < 2; ++jj) {
                    su[ms][0] += ex2(P[ms][jj][0]) + ex2(P[ms][jj][1]);
                    su[ms][1] += ex2(P[ms][jj][2]) + ex2(P[ms][jj][3]);
                }
        }
        __syncthreads();
        if (t + 2 < len) { loadB(t + 2); CP_COMMIT(); }
    }
    // drain final pending parity (last jp wrote parity 1)
#pragma unroll
    for (int ms = 0; ms < 2; ++ms)
#pragma unroll
        for (int jj = 0; jj < 2; ++jj) {
            su[ms][0] += ex2(Cb[1][ms][jj][0]) + ex2(Cb[1][ms][jj][1]);
            su[ms][1] += ex2(Cb[1][ms][jj][2]) + ex2(Cb[1][ms][jj][3]);
        }

    // ---- deterministic reduction ----
#pragma unroll
    for (int ms = 0; ms < 2; ++ms)
#pragma unroll
        for (int h = 0; h < 2; ++h) {
            float x = su[ms][h];
            x += __shfl_xor_sync(0xffffffffu, x, 1);
            x += __shfl_xor_sync(0xffffffffu, x, 2);
            su[ms][h] = x;
        }
    float* sred = (float*)smem;
    if ((lane & 3) == 0) {
#pragma unroll
        for (int ms = 0; ms < 2; ++ms)
#pragma unroll
            for (int h = 0; h < 2; ++h) {
                int srow = warp_m * 32 + ms * 16 + h * 8 + (lane >> 2);
                sred[warp_n * 128 + srow] = su[ms][h];
            }
    }
    __syncthreads();
    if (tid < 128) {
        int u = mtile * NSEG + seg;
        d_partialU[u * 128 + tid] = sred[tid] + sred[128 + tid];
    }
}

// ---------------- final reduction ----------------
__global__ void final_kernel(float* __restrict__ out) {
    __shared__ float sred[512];
    int tid = threadIdx.x;
    float s = 0.f;
    for (int c = tid; c < NC; c += 512) {
        int m = c >> 7, r = c & 127;
        float t = 0.f;
#pragma unroll
        for (int g = 0; g < NSEG; ++g) t += d_partialU[(m * NSEG + g) * 128 + r];
        s += logf(t) - d_tgtlogit[c];
    }
    sred[tid] = s;
    __syncthreads();
#pragma unroll
    for (int o = 256; o; o >>= 1) {
        if (tid < o) sred[tid] += sred[tid + o];
        __syncthreads();
    }
    if (tid == 0) out[0] = sred[0];
}

// ---------------- launch ----------------
extern "C" void kernel_launch(void* const* d_in, const int* in_sizes, int n_in,
                              void* d_out, int out_size) {
    const void*  toks = d_in[0];
    const float* emb  = (const float*)d_in[1];
    const float* Wm   = (const float*)d_in[2];
    float* out = (float*)d_out;

    cudaFuncSetAttribute(gemm_sumexp_kernel,
                         cudaFuncAttributeMaxDynamicSharedMemorySize, SMEM_MAIN);

    convert_kernel<<<LSEQ / 256, 256>>>(toks);
    prep_kernel<<<NCPAD + (VOCAB * DIM / 8 + 127) / 128, 128>>>(emb, Wm);
    gemm_sumexp_kernel<<<dim3(MT, NSEG), 256, SMEM_MAIN>>>();
    final_kernel<<<1, 512>>>(out);
}

// round 6
// speedup vs baseline: 14.1387x; 1.0260x over previous
#include <cuda_runtime.h>
#include <cuda_bf16.h>
#include <math.h>
#include <stdint.h>

// ---------------- problem constants ----------------
#define LSEQ   4096
#define WIN    5
#define NC     4086
#define NCPAD  4096
#define VOCAB  32000
#define DIM    128
#define MT     32              // m-tiles (128 centers each)
#define NSEG   9               // n-segments (7x28 + 2x27 = 250 tiles)
#define NUNITS (MT * NSEG)     // 288 CTAs
#define LOG2E  1.4426950408889634f
#define NEGINF __int_as_float(0xFF800000)

// ---------------- device scratch ----------------
__device__ int            d_tok[LSEQ];
__device__ __nv_bfloat16  d_ctxh[NCPAD * DIM];   // bf16(ctx * log2e)
__device__ __nv_bfloat16  d_Wh[VOCAB * DIM];     // bf16(W)
__device__ float          d_tgtlogit[NCPAD];
__device__ float          d_partialU[NUNITS * 128];
__device__ float          d_blocksum[32];

// ---------------- asm helpers ----------------
__device__ __forceinline__ uint32_t smem_to_u32(const void* p) {
    uint32_t a;
    asm("{ .reg .u64 t; cvta.to.shared.u64 t, %1; cvt.u32.u64 %0, t; }" : "=r"(a) : "l"(p));
    return a;
}
#define CP_ASYNC16(dst, src) \
    asm volatile("cp.async.cg.shared.global [%0], [%1], 16;" :: "r"(dst), "l"(src))
#define CP_COMMIT() asm volatile("cp.async.commit_group;" ::: "memory")
#define CP_WAIT2()  asm volatile("cp.async.wait_group 2;" ::: "memory")

__device__ __forceinline__ void ldsm_x4(uint32_t& r0, uint32_t& r1, uint32_t& r2,
                                        uint32_t& r3, uint32_t addr) {
    asm volatile("ldmatrix.sync.aligned.m8n8.x4.shared.b16 {%0,%1,%2,%3}, [%4];"
                 : "=r"(r0), "=r"(r1), "=r"(r2), "=r"(r3) : "r"(addr));
}
__device__ __forceinline__ void mma_bf16(float* c, const uint32_t* a, const uint32_t* b) {
    asm volatile("mma.sync.aligned.m16n8k16.row.col.f32.bf16.bf16.f32 "
                 "{%0,%1,%2,%3}, {%4,%5,%6,%7}, {%8,%9}, {%0,%1,%2,%3};"
                 : "+f"(c[0]), "+f"(c[1]), "+f"(c[2]), "+f"(c[3])
                 : "r"(a[0]), "r"(a[1]), "r"(a[2]), "r"(a[3]), "r"(b[0]), "r"(b[1]));
}
__device__ __forceinline__ float ex2(float x) {
    float y;
    asm("ex2.approx.f32 %0, %1;" : "=f"(y) : "f"(x));
    return y;
}

// ---------------- prep kernels ----------------
__global__ void convert_kernel(const void* __restrict__ toks) {
    __shared__ int s_is64;
    const int* p = (const int*)toks;
    if (threadIdx.x == 0) {
        int any = 0;
#pragma unroll
        for (int i = 0; i < 16; ++i) any |= p[2 * i + 1];
        s_is64 = (any == 0) ? 1 : 0;
    }
    __syncthreads();
    int i = blockIdx.x * blockDim.x + threadIdx.x;
    if (i >= LSEQ) return;
    if (s_is64) d_tok[i] = (int)(((const long long*)toks)[i]);
    else        d_tok[i] = p[i];
}

// fused: blocks [0,NCPAD) do ctx (+target logit), blocks [NCPAD,..) do W->bf16
__global__ void prep_kernel(const float* __restrict__ emb, const float* __restrict__ Wm) {
    if (blockIdx.x < NCPAD) {
        __shared__ float sred[4];
        int c = blockIdx.x, d = threadIdx.x;
        float s = 0.f;
        if (c < NC) {
#pragma unroll
            for (int j = 0; j < 2 * WIN; ++j) {
                int off = (j < WIN) ? (j - WIN) : (j - WIN + 1);
                int t = d_tok[c + WIN + off];
                s += emb[(size_t)t * DIM + d];
            }
            s *= (1.0f / (2 * WIN));
        }
        d_ctxh[c * DIM + d] = __float2bfloat16(s * LOG2E);
        if (c < NC) {
            int tgt = d_tok[c + WIN];
            float pr = s * Wm[(size_t)tgt * DIM + d];
#pragma unroll
            for (int o = 16; o; o >>= 1) pr += __shfl_xor_sync(0xffffffffu, pr, o);
            if ((d & 31) == 0) sred[d >> 5] = pr;
            __syncthreads();
            if (d == 0) d_tgtlogit[c] = sred[0] + sred[1] + sred[2] + sred[3];
        }
    } else {
        int i = (blockIdx.x - NCPAD) * 128 + threadIdx.x;  // uint4 index
        if (i >= VOCAB * DIM / 8) return;
        float4 w0 = ((const float4*)Wm)[2 * i];
        float4 w1 = ((const float4*)Wm)[2 * i + 1];
        uint4 v;
        v.x = ((uint32_t)__bfloat16_as_ushort(__float2bfloat16(w0.y)) << 16) | __bfloat16_as_ushort(__float2bfloat16(w0.x));
        v.y = ((uint32_t)__bfloat16_as_ushort(__float2bfloat16(w0.w)) << 16) | __bfloat16_as_ushort(__float2bfloat16(w0.z));
        v.z = ((uint32_t)__bfloat16_as_ushort(__float2bfloat16(w1.y)) << 16) | __bfloat16_as_ushort(__float2bfloat16(w1.x));
        v.w = ((uint32_t)__bfloat16_as_ushort(__float2bfloat16(w1.w)) << 16) | __bfloat16_as_ushort(__float2bfloat16(w1.z));
        ((uint4*)d_Wh)[i] = v;
    }
}

// ---------------- main fused GEMM + sum-exp ----------------
// smem: A 32KB | B 3-stage x 32KB = 128KB total
#define SMEM_A_OFF 0
#define SMEM_B_OFF 32768
#define SMEM_MAIN  (32768 + 3 * 32768)

__global__ void __launch_bounds__(256, 1) gemm_sumexp_kernel() {
    extern __shared__ char smem[];
    uint32_t sb = smem_to_u32(smem);
    const int tid  = threadIdx.x;
    const int lane = tid & 31;
    const int wid  = tid >> 5;
    const int warp_m = wid & 3;
    const int warp_n = wid >> 2;
    const int mtile = blockIdx.x;
    const int seg   = blockIdx.y;
    const int nbase = (seg < 7) ? seg * 28 : 196 + (seg - 7) * 27;
    const int len   = (seg < 7) ? 28 : 27;

    const uint32_t sA = sb + SMEM_A_OFF;
    const uint32_t sB = sb + SMEM_B_OFF;

    // ---- async-load A tile (128x128 bf16, swizzled) ----
    {
        const char* src = (const char*)(d_ctxh + (size_t)mtile * 128 * DIM);
#pragma unroll
        for (int i = 0; i < 8; ++i) {
            int j = tid + i * 256;
            int row = j >> 4, cb = j & 15;
            CP_ASYNC16(sA + row * 256 + ((cb ^ (row & 7)) << 4),
                       src + row * 256 + cb * 16);
        }
    }
    auto loadB = [&](int t) {
        const char* src = (const char*)(d_Wh + (size_t)(nbase + t) * 128 * DIM);
        uint32_t dstb = sB + (t % 3) * 32768;
#pragma unroll
        for (int i = 0; i < 8; ++i) {
            int j = tid + i * 256;
            int row = j >> 4, cb = j & 15;
            CP_ASYNC16(dstb + row * 256 + ((cb ^ (row & 7)) << 4),
                       src + row * 256 + cb * 16);
        }
    };
    loadB(0); CP_COMMIT();   // group: A + B0
    loadB(1); CP_COMMIT();
    loadB(2); CP_COMMIT();

    // precomputed B ldsm addressing: row&7 == lane&7 for every (jp,jj)
    const uint32_t rowbase = (uint32_t)(warp_n * 64 + (lane & 7)) * 256;
    uint32_t colsw[4];
#pragma unroll
    for (int kk = 0; kk < 4; ++kk)
        colsw[kk] = (uint32_t)(((kk * 4 + (lane >> 3)) ^ (lane & 7)) << 4);

    uint32_t Afrag[2][8][4];
    uint32_t Bf[2][8][2];             // [jj][ks][2]
    float    C[2][2][4];              // [ms][jj][4] current accumulators
    float    P[2][2][4];              // previous jp stash (being exp'd)
    float    su[2][2] = {{0.f, 0.f}, {0.f, 0.f}};
#pragma unroll
    for (int ms = 0; ms < 2; ++ms)
#pragma unroll
        for (int jj = 0; jj < 2; ++jj)
#pragma unroll
            for (int q = 0; q < 4; ++q) C[ms][jj][q] = NEGINF;

    for (int t = 0; t < len; ++t) {
        CP_WAIT2();
        __syncthreads();
        // prefetch t+2 into stage (t+2)%3 (consumers of that buffer finished
        // tile t-1 before this barrier)
        if (t + 3 <= len - 1 + 1 && t + 2 < len) { loadB(t + 2); CP_COMMIT(); }
        if (t == 0) {
#pragma unroll
            for (int ms = 0; ms < 2; ++ms)
#pragma unroll
                for (int ks = 0; ks < 8; ++ks) {
                    int row = warp_m * 32 + ms * 16 + (lane & 7) + 8 * ((lane >> 3) & 1);
                    int cb  = ks * 2 + (lane >> 4);
                    uint32_t addr = sA + row * 256 + ((cb ^ (row & 7)) << 4);
                    ldsm_x4(Afrag[ms][ks][0], Afrag[ms][ks][1],
                            Afrag[ms][ks][2], Afrag[ms][ks][3], addr);
                }
        }
        const uint32_t tbase = sB + (t % 3) * 32768 + rowbase;

#pragma unroll
        for (int jp = 0; jp < 4; ++jp) {
            // load B fragments for this jp
#pragma unroll
            for (int jj = 0; jj < 2; ++jj) {
                const uint32_t jbase = tbase + (uint32_t)((jp * 16 + jj * 8) * 256);
#pragma unroll
                for (int kk = 0; kk < 4; ++kk)
                    ldsm_x4(Bf[jj][2 * kk][0], Bf[jj][2 * kk][1],
                            Bf[jj][2 * kk + 1][0], Bf[jj][2 * kk + 1][1],
                            jbase + colsw[kk]);
            }
            // stash previous C, reset accumulators
#pragma unroll
            for (int ms = 0; ms < 2; ++ms)
#pragma unroll
                for (int jj = 0; jj < 2; ++jj)
#pragma unroll
                    for (int q = 0; q < 4; ++q) {
                        P[ms][jj][q] = C[ms][jj][q];
                        C[ms][jj][q] = 0.f;
                    }
            // MMA chain with 2 ex2 of previous jp folded into each ks step
#pragma unroll
            for (int ks = 0; ks < 8; ++ks) {
                mma_bf16(C[0][0], Afrag[0][ks], Bf[0][ks]);
                mma_bf16(C[0][1], Afrag[0][ks], Bf[1][ks]);
                mma_bf16(C[1][0], Afrag[1][ks], Bf[0][ks]);
                mma_bf16(C[1][1], Afrag[1][ks], Bf[1][ks]);
                {
                    const int e0 = 2 * ks, e1 = 2 * ks + 1;
                    const int m0 = e0 >> 3, j0 = (e0 >> 2) & 1, q0 = e0 & 3;
                    const int m1 = e1 >> 3, j1 = (e1 >> 2) & 1, q1 = e1 & 3;
                    su[m0][q0 >> 1] += ex2(P[m0][j0][q0]);
                    su[m1][q1 >> 1] += ex2(P[m1][j1][q1]);
                }
            }
        }
    }
    // drain final jp's accumulators
#pragma unroll
    for (int ms = 0; ms < 2; ++ms)
#pragma unroll
        for (int jj = 0; jj < 2; ++jj) {
            su[ms][0] += ex2(C[ms][jj][0]) + ex2(C[ms][jj][1]);
            su[ms][1] += ex2(C[ms][jj][2]) + ex2(C[ms][jj][3]);
        }

    // ---- deterministic reduction ----
#pragma unroll
    for (int ms = 0; ms < 2; ++ms)
#pragma unroll
        for (int h = 0; h < 2; ++h) {
            float x = su[ms][h];
            x += __shfl_xor_sync(0xffffffffu, x, 1);
            x += __shfl_xor_sync(0xffffffffu, x, 2);
            su[ms][h] = x;
        }
    __syncthreads();
    float* sred = (float*)smem;
    if ((lane & 3) == 0) {
#pragma unroll
        for (int ms = 0; ms < 2; ++ms)
#pragma unroll
            for (int h = 0; h < 2; ++h) {
                int srow = warp_m * 32 + ms * 16 + h * 8 + (lane >> 2);
                sred[warp_n * 128 + srow] = su[ms][h];
            }
    }
    __syncthreads();
    if (tid < 128) {
        int u = mtile * NSEG + seg;
        d_partialU[u * 128 + tid] = sred[tid] + sred[128 + tid];
    }
}

// ---------------- loss: per-center, parallel, deterministic ----------------
__global__ void loss_kernel() {
    __shared__ float sred[4];
    int m = blockIdx.x, r = threadIdx.x;
    int c = m * 128 + r;
    float s = 0.f;
    if (c < NC) {
        float t = 0.f;
#pragma unroll
        for (int g = 0; g < NSEG; ++g) t += d_partialU[(m * NSEG + g) * 128 + r];
        s = __logf(t) - d_tgtlogit[c];
    }
#pragma unroll
    for (int o = 16; o; o >>= 1) s += __shfl_xor_sync(0xffffffffu, s, o);
    if ((r & 31) == 0) sred[r >> 5] = s;
    __syncthreads();
    if (r == 0) d_blocksum[m] = sred[0] + sred[1] + sred[2] + sred[3];
}
__global__ void sum_kernel(float* __restrict__ out) {
    int tid = threadIdx.x;
    float s = d_blocksum[tid];
#pragma unroll
    for (int o = 16; o; o >>= 1) s += __shfl_xor_sync(0xffffffffu, s, o);
    if (tid == 0) out[0] = s;
}

// ---------------- launch ----------------
extern "C" void kernel_launch(void* const* d_in, const int* in_sizes, int n_in,
                              void* d_out, int out_size) {
    const void*  toks = d_in[0];
    const float* emb  = (const float*)d_in[1];
    const float* Wm   = (const float*)d_in[2];
    float* out = (float*)d_out;

    cudaFuncSetAttribute(gemm_sumexp_kernel,
                         cudaFuncAttributeMaxDynamicSharedMemorySize, SMEM_MAIN);

    convert_kernel<<<LSEQ / 256, 256>>>(toks);
    prep_kernel<<<NCPAD + (VOCAB * DIM / 8 + 127) / 128, 128>>>(emb, Wm);
    gemm_sumexp_kernel<<<dim3(MT, NSEG), 256, SMEM_MAIN>>>();
    loss_kernel<<<32, 128>>>();
    sum_kernel<<<1, 32>>>(out);
}

// round 7
// speedup vs baseline: 14.4912x; 1.0249x over previous
#include <cuda_runtime.h>
#include <cuda_bf16.h>
#include <math.h>
#include <stdint.h>

// ---------------- problem constants ----------------
#define LSEQ   4096
#define WIN    5
#define NC     4086
#define NCPAD  4096
#define VOCAB  32000
#define DIM    128
#define MT     32              // m-tiles (128 centers each)
#define NSEG   9               // n-segments (7x28 + 2x27 = 250 tiles)
#define NUNITS (MT * NSEG)     // 288 CTAs (one wave at 2 CTAs/SM)
#define LOG2E  1.4426950408889634f

// ---------------- device scratch ----------------
__device__ int            d_tok[LSEQ];
__device__ __nv_bfloat16  d_ctxh[NCPAD * DIM];   // bf16(ctx * log2e)
__device__ __nv_bfloat16  d_Wh[VOCAB * DIM];     // bf16(W)
__device__ float          d_tgtlogit[NCPAD];
__device__ float          d_partialU[NUNITS * 128];
__device__ float          d_blocksum[32];

// ---------------- asm helpers ----------------
__device__ __forceinline__ uint32_t smem_to_u32(const void* p) {
    uint32_t a;
    asm("{ .reg .u64 t; cvta.to.shared.u64 t, %1; cvt.u32.u64 %0, t; }" : "=r"(a) : "l"(p));
    return a;
}
#define CP_ASYNC16(dst, src) \
    asm volatile("cp.async.cg.shared.global [%0], [%1], 16;" :: "r"(dst), "l"(src))
#define CP_COMMIT() asm volatile("cp.async.commit_group;" ::: "memory")
#define CP_WAIT1()  asm volatile("cp.async.wait_group 1;" ::: "memory")

__device__ __forceinline__ void ldsm_x4(uint32_t& r0, uint32_t& r1, uint32_t& r2,
                                        uint32_t& r3, uint32_t addr) {
    asm volatile("ldmatrix.sync.aligned.m8n8.x4.shared.b16 {%0,%1,%2,%3}, [%4];"
                 : "=r"(r0), "=r"(r1), "=r"(r2), "=r"(r3) : "r"(addr));
}
__device__ __forceinline__ void mma_bf16(float* c, const uint32_t* a, const uint32_t* b) {
    asm volatile("mma.sync.aligned.m16n8k16.row.col.f32.bf16.bf16.f32 "
                 "{%0,%1,%2,%3}, {%4,%5,%6,%7}, {%8,%9}, {%0,%1,%2,%3};"
                 : "+f"(c[0]), "+f"(c[1]), "+f"(c[2]), "+f"(c[3])
                 : "r"(a[0]), "r"(a[1]), "r"(a[2]), "r"(a[3]), "r"(b[0]), "r"(b[1]));
}
__device__ __forceinline__ float ex2(float x) {
    float y;
    asm("ex2.approx.f32 %0, %1;" : "=f"(y) : "f"(x));
    return y;
}

// ---------------- prep kernels ----------------
__global__ void convert_kernel(const void* __restrict__ toks) {
    __shared__ int s_is64;
    const int* p = (const int*)toks;
    if (threadIdx.x == 0) {
        int any = 0;
#pragma unroll
        for (int i = 0; i < 16; ++i) any |= p[2 * i + 1];
        s_is64 = (any == 0) ? 1 : 0;
    }
    __syncthreads();
    int i = blockIdx.x * blockDim.x + threadIdx.x;
    if (i >= LSEQ) return;
    if (s_is64) d_tok[i] = (int)(((const long long*)toks)[i]);
    else        d_tok[i] = p[i];
}

// fused: blocks [0,NCPAD) do ctx (+target logit), blocks [NCPAD,..) do W->bf16
__global__ void prep_kernel(const float* __restrict__ emb, const float* __restrict__ Wm) {
    if (blockIdx.x < NCPAD) {
        __shared__ float sred[4];
        int c = blockIdx.x, d = threadIdx.x;
        float s = 0.f;
        if (c < NC) {
#pragma unroll
            for (int j = 0; j < 2 * WIN; ++j) {
                int off = (j < WIN) ? (j - WIN) : (j - WIN + 1);
                int t = d_tok[c + WIN + off];
                s += emb[(size_t)t * DIM + d];
            }
            s *= (1.0f / (2 * WIN));
        }
        d_ctxh[c * DIM + d] = __float2bfloat16(s * LOG2E);
        if (c < NC) {
            int tgt = d_tok[c + WIN];
            float pr = s * Wm[(size_t)tgt * DIM + d];
#pragma unroll
            for (int o = 16; o; o >>= 1) pr += __shfl_xor_sync(0xffffffffu, pr, o);
            if ((d & 31) == 0) sred[d >> 5] = pr;
            __syncthreads();
            if (d == 0) d_tgtlogit[c] = sred[0] + sred[1] + sred[2] + sred[3];
        }
    } else {
        int i = (blockIdx.x - NCPAD) * 128 + threadIdx.x;  // uint4 index
        if (i >= VOCAB * DIM / 8) return;
        float4 w0 = ((const float4*)Wm)[2 * i];
        float4 w1 = ((const float4*)Wm)[2 * i + 1];
        uint4 v;
        v.x = ((uint32_t)__bfloat16_as_ushort(__float2bfloat16(w0.y)) << 16) | __bfloat16_as_ushort(__float2bfloat16(w0.x));
        v.y = ((uint32_t)__bfloat16_as_ushort(__float2bfloat16(w0.w)) << 16) | __bfloat16_as_ushort(__float2bfloat16(w0.z));
        v.z = ((uint32_t)__bfloat16_as_ushort(__float2bfloat16(w1.y)) << 16) | __bfloat16_as_ushort(__float2bfloat16(w1.x));
        v.w = ((uint32_t)__bfloat16_as_ushort(__float2bfloat16(w1.w)) << 16) | __bfloat16_as_ushort(__float2bfloat16(w1.z));
        ((uint4*)d_Wh)[i] = v;
    }
}

// ---------------- main fused GEMM + sum-exp ----------------
// 2 CTAs/SM: smem per CTA = A 32KB + 2-stage B 64KB = 96KB; regs <= 128.
#define SMEM_A_OFF 0
#define SMEM_B_OFF 32768
#define SMEM_MAIN  (32768 + 2 * 32768)

__global__ void __launch_bounds__(256, 2) gemm_sumexp_kernel() {
    extern __shared__ char smem[];
    uint32_t sb = smem_to_u32(smem);
    const int tid  = threadIdx.x;
    const int lane = tid & 31;
    const int wid  = tid >> 5;
    const int warp_m = wid & 3;
    const int warp_n = wid >> 2;
    const int mtile = blockIdx.x;
    const int seg   = blockIdx.y;
    const int nbase = (seg < 7) ? seg * 28 : 196 + (seg - 7) * 27;
    const int len   = (seg < 7) ? 28 : 27;

    const uint32_t sA = sb + SMEM_A_OFF;
    const uint32_t sB = sb + SMEM_B_OFF;

    // ---- async-load A tile (128x128 bf16, swizzled) ----
    {
        const char* src = (const char*)(d_ctxh + (size_t)mtile * 128 * DIM);
#pragma unroll
        for (int i = 0; i < 8; ++i) {
            int j = tid + i * 256;
            int row = j >> 4, cb = j & 15;
            CP_ASYNC16(sA + row * 256 + ((cb ^ (row & 7)) << 4),
                       src + row * 256 + cb * 16);
        }
    }
    auto loadB = [&](int t) {
        const char* src = (const char*)(d_Wh + (size_t)(nbase + t) * 128 * DIM);
        uint32_t dstb = sB + (t & 1) * 32768;
#pragma unroll
        for (int i = 0; i < 8; ++i) {
            int j = tid + i * 256;
            int row = j >> 4, cb = j & 15;
            CP_ASYNC16(dstb + row * 256 + ((cb ^ (row & 7)) << 4),
                       src + row * 256 + cb * 16);
        }
    };
    loadB(0); CP_COMMIT();   // group: A + B0
    loadB(1); CP_COMMIT();

    // B ldsm addressing: row&7 == lane&7 for all chunks
    const uint32_t rowbase = (uint32_t)(warp_n * 64 + (lane & 7)) * 256;
    uint32_t colsw[4];
#pragma unroll
    for (int kk = 0; kk < 4; ++kk)
        colsw[kk] = (uint32_t)(((kk * 4 + (lane >> 3)) ^ (lane & 7)) << 4);

    uint32_t Afrag[2][8][4];          // persistent A fragments (64 regs)
    float    su[2][2] = {{0.f, 0.f}, {0.f, 0.f}};

    for (int t = 0; t < len; ++t) {
        CP_WAIT1();
        __syncthreads();
        if (t == 0) {
#pragma unroll
            for (int ms = 0; ms < 2; ++ms)
#pragma unroll
                for (int ks = 0; ks < 8; ++ks) {
                    int row = warp_m * 32 + ms * 16 + (lane & 7) + 8 * ((lane >> 3) & 1);
                    int cb  = ks * 2 + (lane >> 4);
                    uint32_t addr = sA + row * 256 + ((cb ^ (row & 7)) << 4);
                    ldsm_x4(Afrag[ms][ks][0], Afrag[ms][ks][1],
                            Afrag[ms][ks][2], Afrag[ms][ks][3], addr);
                }
        }
        const uint32_t tbase = sB + (t & 1) * 32768 + rowbase;

        // 8 n8-chunks, processed one at a time (small live set; cross-warp
        // overlap at 4 warps/SMSP hides the ex2 phase under other warps' MMAs)
#pragma unroll
        for (int j8 = 0; j8 < 8; ++j8) {
            uint32_t Bf[8][2];
            const uint32_t jbase = tbase + (uint32_t)(j8 * 8 * 256);
#pragma unroll
            for (int kk = 0; kk < 4; ++kk)
                ldsm_x4(Bf[2 * kk][0], Bf[2 * kk][1],
                        Bf[2 * kk + 1][0], Bf[2 * kk + 1][1],
                        jbase + colsw[kk]);
            float C0[4] = {0.f, 0.f, 0.f, 0.f};
            float C1[4] = {0.f, 0.f, 0.f, 0.f};
#pragma unroll
            for (int ks = 0; ks < 8; ++ks) {
                mma_bf16(C0, Afrag[0][ks], Bf[ks]);
                mma_bf16(C1, Afrag[1][ks], Bf[ks]);
            }
            su[0][0] += ex2(C0[0]) + ex2(C0[1]);
            su[0][1] += ex2(C0[2]) + ex2(C0[3]);
            su[1][0] += ex2(C1[0]) + ex2(C1[1]);
            su[1][1] += ex2(C1[2]) + ex2(C1[3]);
        }
        __syncthreads();
        if (t + 2 < len) { loadB(t + 2); CP_COMMIT(); }
    }

    // ---- deterministic reduction ----
#pragma unroll
    for (int ms = 0; ms < 2; ++ms)
#pragma unroll
        for (int h = 0; h < 2; ++h) {
            float x = su[ms][h];
            x += __shfl_xor_sync(0xffffffffu, x, 1);
            x += __shfl_xor_sync(0xffffffffu, x, 2);
            su[ms][h] = x;
        }
    __syncthreads();
    float* sred = (float*)smem;
    if ((lane & 3) == 0) {
#pragma unroll
        for (int ms = 0; ms < 2; ++ms)
#pragma unroll
            for (int h = 0; h < 2; ++h) {
                int srow = warp_m * 32 + ms * 16 + h * 8 + (lane >> 2);
                sred[warp_n * 128 + srow] = su[ms][h];
            }
    }
    __syncthreads();
    if (tid < 128) {
        int u = mtile * NSEG + seg;
        d_partialU[u * 128 + tid] = sred[tid] + sred[128 + tid];
    }
}

// ---------------- loss: per-center, parallel, deterministic ----------------
__global__ void loss_kernel() {
    __shared__ float sred[4];
    int m = blockIdx.x, r = threadIdx.x;
    int c = m * 128 + r;
    float s = 0.f;
    if (c < NC) {
        float t = 0.f;
#pragma unroll
        for (int g = 0; g < NSEG; ++g) t += d_partialU[(m * NSEG + g) * 128 + r];
        s = __logf(t) - d_tgtlogit[c];
    }
#pragma unroll
    for (int o = 16; o; o >>= 1) s += __shfl_xor_sync(0xffffffffu, s, o);
    if ((r & 31) == 0) sred[r >> 5] = s;
    __syncthreads();
    if (r == 0) d_blocksum[m] = sred[0] + sred[1] + sred[2] + sred[3];
}
__global__ void sum_kernel(float* __restrict__ out) {
    int tid = threadIdx.x;
    float s = d_blocksum[tid];
#pragma unroll
    for (int o = 16; o; o >>= 1) s += __shfl_xor_sync(0xffffffffu, s, o);
    if (tid == 0) out[0] = s;
}

// ---------------- launch ----------------
extern "C" void kernel_launch(void* const* d_in, const int* in_sizes, int n_in,
                              void* d_out, int out_size) {
    const void*  toks = d_in[0];
    const float* emb  = (const float*)d_in[1];
    const float* Wm   = (const float*)d_in[2];
    float* out = (float*)d_out;

    cudaFuncSetAttribute(gemm_sumexp_kernel,
                         cudaFuncAttributeMaxDynamicSharedMemorySize, SMEM_MAIN);

    convert_kernel<<<LSEQ / 256, 256>>>(toks);
    prep_kernel<<<NCPAD + (VOCAB * DIM / 8 + 127) / 128, 128>>>(emb, Wm);
    gemm_sumexp_kernel<<<dim3(MT, NSEG), 256, SMEM_MAIN>>>();
    loss_kernel<<<32, 128>>>();
    sum_kernel<<<1, 32>>>(out);
}